// round 4
// baseline (speedup 1.0000x reference)
#include <cuda_runtime.h>
#include <cstdint>

// Problem constants
#define BSZ 8
#define SEQ 1024
#define NX  1024
#define NH  16
#define HD  64

#define GELEMS (8u * 1024u * 1024u)

__device__ float g_q[GELEMS];
__device__ float g_k[GELEMS];
__device__ float g_v[GELEMS];
__device__ float g_a[GELEMS];

// ---------------------------------------------------------------------------
// tf32 helpers
// ---------------------------------------------------------------------------
__device__ __forceinline__ uint32_t f2tf32(float f) {
    uint32_t r;
    asm("cvt.rna.tf32.f32 %0, %1;" : "=r"(r) : "f"(f));
    return r;
}

__device__ __forceinline__ void mma_tf32(float c[4], const uint32_t a[4],
                                         const uint32_t b[2]) {
    asm volatile(
        "mma.sync.aligned.m16n8k8.row.col.f32.tf32.tf32.f32 "
        "{%0,%1,%2,%3}, {%4,%5,%6,%7}, {%8,%9}, {%0,%1,%2,%3};\n"
        : "+f"(c[0]), "+f"(c[1]), "+f"(c[2]), "+f"(c[3])
        : "r"(a[0]), "r"(a[1]), "r"(a[2]), "r"(a[3]), "r"(b[0]), "r"(b[1]));
}

// ---------------------------------------------------------------------------
// Double-buffered tf32 GEMM tile body.
// CTA 128x128, 128 threads = 4 warps (2m x 2n), warp tile 64x64.
// K-step 32, one __syncthreads per K-iter, LDG overlapped with MMA.
// Smem pitch 136 -> fragment reads bank-conflict-free (8*tg+gid bijective).
// ---------------------------------------------------------------------------
#define GPITCH 136
#define KSTEP  32
#define GSMEM  (4 * KSTEP * GPITCH * 4)   // A0,A1,B0,B1 = 69632 bytes

__device__ __forceinline__ void gemm_tile(
    const float* __restrict__ A, const float* __restrict__ W,
    const float* __restrict__ bias, float* __restrict__ C,
    int K, int ldw, int ldc, int m0, int n0w, int n0c)
{
    extern __shared__ uint32_t smg[];
    uint32_t* Asb[2] = { smg,                 smg + KSTEP * GPITCH };
    uint32_t* Bsb[2] = { smg + 2 * KSTEP * GPITCH, smg + 3 * KSTEP * GPITCH };

    const int tid  = threadIdx.x;
    const int wid  = tid >> 5;
    const int lane = tid & 31;
    const int gid  = lane >> 2;
    const int tg   = lane & 3;
    const int wm   = (wid & 1) * 64;
    const int wn   = (wid >> 1) * 64;

    const float* Ap = A + (long)(m0 + tid) * K;   // one A row per thread
    const int brow0 = tid >> 5;                    // B row within tile (+4 per t)
    const int bcol  = lane * 4;

    float acc[4][8][4];
#pragma unroll
    for (int i = 0; i < 4; ++i)
#pragma unroll
        for (int j = 0; j < 8; ++j)
#pragma unroll
            for (int r = 0; r < 4; ++r) acc[i][j][r] = 0.0f;

    float4 areg[8], breg[8];

    // ---- prologue: load tile 0, store to buffer 0 ----
#pragma unroll
    for (int t = 0; t < 8; ++t) areg[t] = *(const float4*)(Ap + t * 4);
#pragma unroll
    for (int t = 0; t < 8; ++t)
        breg[t] = *(const float4*)(W + (long)(brow0 + t * 4) * ldw + n0w + bcol);
    {
        uint32_t* as = Asb[0];
        uint32_t* bs = Bsb[0];
#pragma unroll
        for (int t = 0; t < 8; ++t) {
            int kc = t * 4;
            as[(kc + 0) * GPITCH + tid] = f2tf32(areg[t].x);
            as[(kc + 1) * GPITCH + tid] = f2tf32(areg[t].y);
            as[(kc + 2) * GPITCH + tid] = f2tf32(areg[t].z);
            as[(kc + 3) * GPITCH + tid] = f2tf32(areg[t].w);
        }
#pragma unroll
        for (int t = 0; t < 8; ++t) {
            uint32_t* p = &bs[(brow0 + t * 4) * GPITCH + bcol];
            p[0] = f2tf32(breg[t].x); p[1] = f2tf32(breg[t].y);
            p[2] = f2tf32(breg[t].z); p[3] = f2tf32(breg[t].w);
        }
    }
    __syncthreads();

    const int nkt = K / KSTEP;
    for (int kt = 0; kt < nkt; ++kt) {
        const int cur = kt & 1;
        const bool more = (kt + 1 < nkt);

        // Issue next-tile global loads first (latency hidden under MMAs)
        if (more) {
            const float* ap = Ap + (kt + 1) * KSTEP;
#pragma unroll
            for (int t = 0; t < 8; ++t) areg[t] = *(const float4*)(ap + t * 4);
#pragma unroll
            for (int t = 0; t < 8; ++t)
                breg[t] = *(const float4*)(W +
                    (long)((kt + 1) * KSTEP + brow0 + t * 4) * ldw + n0w + bcol);
        }

        // Compute on current buffer
        const uint32_t* as = Asb[cur];
        const uint32_t* bs = Bsb[cur];
#pragma unroll
        for (int k8 = 0; k8 < 4; ++k8) {
            const int kb = k8 * 8;
            uint32_t afr[4][4], bfr[8][2];
#pragma unroll
            for (int mf = 0; mf < 4; ++mf) {
                int mrow = wm + mf * 16 + gid;
                afr[mf][0] = as[(kb + tg) * GPITCH + mrow];
                afr[mf][1] = as[(kb + tg) * GPITCH + mrow + 8];
                afr[mf][2] = as[(kb + tg + 4) * GPITCH + mrow];
                afr[mf][3] = as[(kb + tg + 4) * GPITCH + mrow + 8];
            }
#pragma unroll
            for (int nf = 0; nf < 8; ++nf) {
                int ncol = wn + nf * 8 + gid;
                bfr[nf][0] = bs[(kb + tg) * GPITCH + ncol];
                bfr[nf][1] = bs[(kb + tg + 4) * GPITCH + ncol];
            }
#pragma unroll
            for (int mf = 0; mf < 4; ++mf)
#pragma unroll
                for (int nf = 0; nf < 8; ++nf)
                    mma_tf32(acc[mf][nf], afr[mf], bfr[nf]);
        }

        // Store next tile into the other buffer
        if (more) {
            uint32_t* asn = Asb[1 - cur];
            uint32_t* bsn = Bsb[1 - cur];
#pragma unroll
            for (int t = 0; t < 8; ++t) {
                int kc = t * 4;
                asn[(kc + 0) * GPITCH + tid] = f2tf32(areg[t].x);
                asn[(kc + 1) * GPITCH + tid] = f2tf32(areg[t].y);
                asn[(kc + 2) * GPITCH + tid] = f2tf32(areg[t].z);
                asn[(kc + 3) * GPITCH + tid] = f2tf32(areg[t].w);
            }
#pragma unroll
            for (int t = 0; t < 8; ++t) {
                uint32_t* p = &bsn[(brow0 + t * 4) * GPITCH + bcol];
                p[0] = f2tf32(breg[t].x); p[1] = f2tf32(breg[t].y);
                p[2] = f2tf32(breg[t].z); p[3] = f2tf32(breg[t].w);
            }
        }
        __syncthreads();
    }

    // ---- epilogue: bias + store ----
#pragma unroll
    for (int nf = 0; nf < 8; ++nf) {
        int colw = n0w + wn + nf * 8 + tg * 2;
        int colc = n0c + wn + nf * 8 + tg * 2;
        float b0 = bias[colw], b1 = bias[colw + 1];
#pragma unroll
        for (int mf = 0; mf < 4; ++mf) {
            int row0 = m0 + wm + mf * 16 + gid;
            *(float2*)(C + (long)row0 * ldc + colc) =
                make_float2(acc[mf][nf][0] + b0, acc[mf][nf][1] + b1);
            *(float2*)(C + (long)(row0 + 8) * ldc + colc) =
                make_float2(acc[mf][nf][2] + b0, acc[mf][nf][3] + b1);
        }
    }
}

// Fused QKV projection: grid (3072/128, 8192/128). Per-n-block A/C select.
__global__ __launch_bounds__(128) void qkv_gemm_kernel(
    const float* __restrict__ x, const float* __restrict__ query,
    const float* __restrict__ attw, const float* __restrict__ attb,
    float* __restrict__ gq, float* __restrict__ gk, float* __restrict__ gv)
{
    const int n0g = blockIdx.x * 128;    // 0..2944
    const int m0  = blockIdx.y * 128;
    const float* A = (n0g < NX) ? query : x;
    float* C;
    int n0c;
    if (n0g < NX)          { C = gq; n0c = n0g; }
    else if (n0g < 2 * NX) { C = gk; n0c = n0g - NX; }
    else                   { C = gv; n0c = n0g - 2 * NX; }
    gemm_tile(A, attw, attb, C, NX, 3 * NX, NX, m0, n0g, n0c);
}

// Output projection: grid (1024/128, 8192/128).
__global__ __launch_bounds__(128) void proj_gemm_kernel(
    const float* __restrict__ Ain, const float* __restrict__ projw,
    const float* __restrict__ projb, float* __restrict__ out)
{
    const int n0 = blockIdx.x * 128;
    const int m0 = blockIdx.y * 128;
    gemm_tile(Ain, projw, projb, out, NX, NX, NX, m0, n0, n0);
}

// ---------------------------------------------------------------------------
// Flash attention with tf32 tensor-core MMA (unchanged from R3).
// ---------------------------------------------------------------------------
#define BQ 128
#define BK 64
#define APD 68
#define ATT_SMEM ((BQ + BK + BK) * APD * 4)

__global__ __launch_bounds__(256) void attn_kernel(
    const float* __restrict__ Qg, const float* __restrict__ Kg,
    const float* __restrict__ Vg, float* __restrict__ Og)
{
    extern __shared__ uint32_t sm4[];
    uint32_t* PQ = sm4;
    uint32_t* Ks = PQ + BQ * APD;
    uint32_t* Vs = Ks + BK * APD;

    const int qb = blockIdx.x;
    const int h  = blockIdx.y;
    const int b  = blockIdx.z;
    const int tid  = threadIdx.x;
    const int wid  = tid >> 5;
    const int lane = tid & 31;
    const int gid  = lane >> 2;
    const int tg   = lane & 3;

    const int r0 = wid * 16 + gid;
    const int r1 = r0 + 8;
    const float scale = 0.125f;

    {
        const float* base = Qg + ((long)(b * SEQ + qb * BQ)) * NX + h * HD;
#pragma unroll
        for (int t = 0; t < 8; ++t) {
            int id = tid + t * 256;
            int r = id >> 4;
            int d4 = (id & 15) * 4;
            float4 v = *(const float4*)(base + (long)r * NX + d4);
            uint32_t* p = &PQ[r * APD + d4];
            p[0] = f2tf32(v.x * scale);
            p[1] = f2tf32(v.y * scale);
            p[2] = f2tf32(v.z * scale);
            p[3] = f2tf32(v.w * scale);
        }
    }
    __syncthreads();

    uint32_t qf[8][4];
#pragma unroll
    for (int ks = 0; ks < 8; ++ks) {
        int kc = ks * 8 + tg;
        qf[ks][0] = PQ[r0 * APD + kc];
        qf[ks][1] = PQ[r1 * APD + kc];
        qf[ks][2] = PQ[r0 * APD + kc + 4];
        qf[ks][3] = PQ[r1 * APD + kc + 4];
    }

    float m_i[2] = {-3.0e38f, -3.0e38f};
    float l_i[2] = {0.0f, 0.0f};
    float O[8][4];
#pragma unroll
    for (int nf = 0; nf < 8; ++nf)
#pragma unroll
        for (int r = 0; r < 4; ++r) O[nf][r] = 0.0f;

    const int nkb = 2 * qb + 2;

    for (int kb = 0; kb < nkb; ++kb) {
        __syncthreads();
        {
            const float* kbase = Kg + ((long)(b * SEQ + kb * BK)) * NX + h * HD;
            const float* vbase = Vg + ((long)(b * SEQ + kb * BK)) * NX + h * HD;
#pragma unroll
            for (int t = 0; t < 4; ++t) {
                int id = tid + t * 256;
                int r = id >> 4;
                int d4 = (id & 15) * 4;
                float4 kv = *(const float4*)(kbase + (long)r * NX + d4);
                float4 vv = *(const float4*)(vbase + (long)r * NX + d4);
                uint32_t* pk = &Ks[r * APD + d4];
                pk[0] = f2tf32(kv.x); pk[1] = f2tf32(kv.y);
                pk[2] = f2tf32(kv.z); pk[3] = f2tf32(kv.w);
                uint32_t* pv = &Vs[r * APD + d4];
                pv[0] = f2tf32(vv.x); pv[1] = f2tf32(vv.y);
                pv[2] = f2tf32(vv.z); pv[3] = f2tf32(vv.w);
            }
        }
        __syncthreads();

        float s[8][4];
#pragma unroll
        for (int nf = 0; nf < 8; ++nf)
#pragma unroll
            for (int r = 0; r < 4; ++r) s[nf][r] = 0.0f;

#pragma unroll
        for (int ks = 0; ks < 8; ++ks) {
            int kc = ks * 8 + tg;
#pragma unroll
            for (int nf = 0; nf < 8; ++nf) {
                uint32_t bfr[2];
                int key = nf * 8 + gid;
                bfr[0] = Ks[key * APD + kc];
                bfr[1] = Ks[key * APD + kc + 4];
                mma_tf32(s[nf], qf[ks], bfr);
            }
        }

        if (kb >= 2 * qb) {
            const int grow0 = qb * BQ + r0;
            const int gcol0 = kb * BK + 2 * tg;
#pragma unroll
            for (int nf = 0; nf < 8; ++nf) {
                int c = gcol0 + nf * 8;
                if (c     > grow0)     s[nf][0] = -10000.0f;
                if (c + 1 > grow0)     s[nf][1] = -10000.0f;
                if (c     > grow0 + 8) s[nf][2] = -10000.0f;
                if (c + 1 > grow0 + 8) s[nf][3] = -10000.0f;
            }
        }

        float rm0 = s[0][0], rm1 = s[0][2];
#pragma unroll
        for (int nf = 0; nf < 8; ++nf) {
            rm0 = fmaxf(rm0, fmaxf(s[nf][0], s[nf][1]));
            rm1 = fmaxf(rm1, fmaxf(s[nf][2], s[nf][3]));
        }
        rm0 = fmaxf(rm0, __shfl_xor_sync(0xffffffffu, rm0, 1));
        rm0 = fmaxf(rm0, __shfl_xor_sync(0xffffffffu, rm0, 2));
        rm1 = fmaxf(rm1, __shfl_xor_sync(0xffffffffu, rm1, 1));
        rm1 = fmaxf(rm1, __shfl_xor_sync(0xffffffffu, rm1, 2));

        float mn0 = fmaxf(m_i[0], rm0);
        float mn1 = fmaxf(m_i[1], rm1);
        float alpha0 = __expf(m_i[0] - mn0);
        float alpha1 = __expf(m_i[1] - mn1);
        m_i[0] = mn0; m_i[1] = mn1;

        float ls0 = 0.0f, ls1 = 0.0f;
#pragma unroll
        for (int nf = 0; nf < 8; ++nf) {
            float p0 = __expf(s[nf][0] - mn0);
            float p1 = __expf(s[nf][1] - mn0);
            float p2 = __expf(s[nf][2] - mn1);
            float p3 = __expf(s[nf][3] - mn1);
            ls0 += p0 + p1;
            ls1 += p2 + p3;
            int col = nf * 8 + 2 * tg;
            *(uint2*)&PQ[r0 * APD + col] = make_uint2(f2tf32(p0), f2tf32(p1));
            *(uint2*)&PQ[r1 * APD + col] = make_uint2(f2tf32(p2), f2tf32(p3));
        }
        ls0 += __shfl_xor_sync(0xffffffffu, ls0, 1);
        ls0 += __shfl_xor_sync(0xffffffffu, ls0, 2);
        ls1 += __shfl_xor_sync(0xffffffffu, ls1, 1);
        ls1 += __shfl_xor_sync(0xffffffffu, ls1, 2);

        l_i[0] = l_i[0] * alpha0 + ls0;
        l_i[1] = l_i[1] * alpha1 + ls1;
#pragma unroll
        for (int nf = 0; nf < 8; ++nf) {
            O[nf][0] *= alpha0; O[nf][1] *= alpha0;
            O[nf][2] *= alpha1; O[nf][3] *= alpha1;
        }

        __syncwarp();

#pragma unroll
        for (int ks = 0; ks < 8; ++ks) {
            int kc = ks * 8 + tg;
            uint32_t af[4];
            af[0] = PQ[r0 * APD + kc];
            af[1] = PQ[r1 * APD + kc];
            af[2] = PQ[r0 * APD + kc + 4];
            af[3] = PQ[r1 * APD + kc + 4];
#pragma unroll
            for (int nf = 0; nf < 8; ++nf) {
                uint32_t bfr[2];
                int d = nf * 8 + gid;
                bfr[0] = Vs[kc * APD + d];
                bfr[1] = Vs[(kc + 4) * APD + d];
                mma_tf32(O[nf], af, bfr);
            }
        }
        __syncwarp();
    }

    float inv0 = 1.0f / l_i[0];
    float inv1 = 1.0f / l_i[1];
    const long orow0 = (long)(b * SEQ + qb * BQ + r0);
#pragma unroll
    for (int nf = 0; nf < 8; ++nf) {
        int col = h * HD + nf * 8 + 2 * tg;
        *(float2*)(Og + orow0 * NX + col) =
            make_float2(O[nf][0] * inv0, O[nf][1] * inv0);
        *(float2*)(Og + (orow0 + 8) * NX + col) =
            make_float2(O[nf][2] * inv1, O[nf][3] * inv1);
    }
}

// ---------------------------------------------------------------------------
// Launch
// ---------------------------------------------------------------------------
extern "C" void kernel_launch(void* const* d_in, const int* in_sizes, int n_in,
                              void* d_out, int out_size)
{
    const float* x     = (const float*)d_in[0];
    const float* query = (const float*)d_in[1];
    const float* attw  = (const float*)d_in[2];
    const float* attb  = (const float*)d_in[3];
    const float* projw = (const float*)d_in[4];
    const float* projb = (const float*)d_in[5];
    float* out = (float*)d_out;

    float *qb_, *kb_, *vb_, *ab_;
    cudaGetSymbolAddress((void**)&qb_, g_q);
    cudaGetSymbolAddress((void**)&kb_, g_k);
    cudaGetSymbolAddress((void**)&vb_, g_v);
    cudaGetSymbolAddress((void**)&ab_, g_a);

    cudaFuncSetAttribute(qkv_gemm_kernel,
                         cudaFuncAttributeMaxDynamicSharedMemorySize, GSMEM);
    cudaFuncSetAttribute(proj_gemm_kernel,
                         cudaFuncAttributeMaxDynamicSharedMemorySize, GSMEM);
    cudaFuncSetAttribute(attn_kernel,
                         cudaFuncAttributeMaxDynamicSharedMemorySize, ATT_SMEM);

    const int M = BSZ * SEQ;   // 8192

    // Fused q/k/v projections over N=3072
    qkv_gemm_kernel<<<dim3(3 * NX / 128, M / 128), 128, GSMEM>>>(
        x, query, attw, attb, qb_, kb_, vb_);

    // Attention -> merged heads
    attn_kernel<<<dim3(SEQ / BQ, NH, BSZ), 256, ATT_SMEM>>>(qb_, kb_, vb_, ab_);

    // Output projection
    proj_gemm_kernel<<<dim3(NX / 128, M / 128), 128, GSMEM>>>(
        ab_, projw, projb, out);
}

// round 6
// speedup vs baseline: 1.7338x; 1.7338x over previous
#include <cuda_runtime.h>
#include <cuda_fp16.h>
#include <cstdint>

// Problem constants
#define BSZ 8
#define SEQ 1024
#define NX  1024
#define NH  16
#define HD  64

// All half-precision buffers stored as uint32 words (2 halves per word)
__device__ uint32_t b_inq[8192 * 512];   // query, fp16
__device__ uint32_t b_inx[8192 * 512];   // x, fp16
__device__ uint32_t b_w2[512 * 3072];    // attw packed: [k2][n], word=(k even, k odd)
__device__ uint32_t b_p2[512 * 1024];    // projw packed
__device__ uint32_t b_q[8192 * 512];     // q*0.125, fp16
__device__ uint32_t b_k[8192 * 512];
__device__ uint32_t b_v[8192 * 512];
__device__ uint32_t b_a[8192 * 512];     // attention out, fp16

// ---------------------------------------------------------------------------
// helpers
// ---------------------------------------------------------------------------
__device__ __forceinline__ uint32_t pack_h2(float lo, float hi) {
    uint32_t d;
    asm("cvt.rn.f16x2.f32 %0, %1, %2;" : "=r"(d) : "f"(hi), "f"(lo));
    return d;
}
__device__ __forceinline__ uint32_t prmt(uint32_t a, uint32_t b, uint32_t sel) {
    uint32_t d;
    asm("prmt.b32 %0, %1, %2, %3;" : "=r"(d) : "r"(a), "r"(b), "r"(sel));
    return d;
}
__device__ __forceinline__ void mma_f16(float c[4], const uint32_t a[4],
                                        const uint32_t b[2]) {
    asm volatile(
        "mma.sync.aligned.m16n8k16.row.col.f32.f16.f16.f32 "
        "{%0,%1,%2,%3}, {%4,%5,%6,%7}, {%8,%9}, {%0,%1,%2,%3};\n"
        : "+f"(c[0]), "+f"(c[1]), "+f"(c[2]), "+f"(c[3])
        : "r"(a[0]), "r"(a[1]), "r"(a[2]), "r"(a[3]), "r"(b[0]), "r"(b[1]));
}

// ---------------------------------------------------------------------------
// pre-passes
// ---------------------------------------------------------------------------
__global__ __launch_bounds__(256) void cvt_f16_kernel(
    const float4* __restrict__ q, const float4* __restrict__ x)
{
    const size_t i = (size_t)blockIdx.x * 256 + threadIdx.x;
    const float4 f = (blockIdx.y == 0) ? q[i] : x[i];
    uint32_t* o = (blockIdx.y == 0) ? b_inq : b_inx;
    o[2 * i]     = pack_h2(f.x, f.y);
    o[2 * i + 1] = pack_h2(f.z, f.w);
}

// W [1024][N] f32 -> out [512][N] words, word n = (W[2k2][n], W[2k2+1][n])
__global__ __launch_bounds__(256) void packw_kernel(
    const float* __restrict__ W, int N, uint32_t* __restrict__ out)
{
    const int n4 = blockIdx.x * 256 + threadIdx.x;
    const int k2 = blockIdx.y;
    const float4 e = *(const float4*)(W + (size_t)(2 * k2) * N + 4 * n4);
    const float4 o = *(const float4*)(W + (size_t)(2 * k2 + 1) * N + 4 * n4);
    uint4 r;
    r.x = pack_h2(e.x, o.x); r.y = pack_h2(e.y, o.y);
    r.z = pack_h2(e.z, o.z); r.w = pack_h2(e.w, o.w);
    *(uint4*)(out + (size_t)k2 * N + 4 * n4) = r;
}

// ---------------------------------------------------------------------------
// fp16 GEMM mainloop (shared by qkv / proj): CTA 128x128, 256 thr = 8 warps
// (2m x 4n), warp 64x32, k-step 64 halves (32 k2 rows, 4 k16 chunks).
// As[m][k] halves pitch 72 (36 words); Bs[k2][n] words pitch 136.
// ---------------------------------------------------------------------------
#define GEMM_MAIN(AGPTR, WGPTR, LDW2)                                          \
    __shared__ __align__(16) uint32_t As[128 * 36];                            \
    __shared__ __align__(16) uint32_t Bs[32 * 136];                            \
    const int t = threadIdx.x;                                                 \
    const int warp = t >> 5, lane = t & 31;                                    \
    const int gid = lane >> 2, tg = lane & 3;                                  \
    const int wm = (warp & 1) * 64, wn = (warp >> 1) * 32;                     \
    const int sr = t >> 3;                                                     \
    const int si = (t & 7) * 4;                                                \
    float acc[4][4][4];                                                        \
    _Pragma("unroll") for (int i = 0; i < 4; ++i)                              \
    _Pragma("unroll") for (int j = 0; j < 4; ++j)                              \
    _Pragma("unroll") for (int r = 0; r < 4; ++r) acc[i][j][r] = 0.0f;         \
    for (int kt = 0; kt < 16; ++kt) {                                          \
        uint4 av[4], bv[4];                                                    \
        _Pragma("unroll")                                                      \
        for (int rr = 0; rr < 4; ++rr)                                         \
            av[rr] = *(const uint4*)(AGPTR +                                   \
                (size_t)(m0 + sr + rr * 32) * 512 + kt * 32 + si);             \
        _Pragma("unroll")                                                      \
        for (int ii = 0; ii < 4; ++ii)                                         \
            bv[ii] = *(const uint4*)(WGPTR +                                   \
                (size_t)(kt * 32 + sr) * (LDW2) + ng + si + ii * 32);          \
        __syncthreads();                                                       \
        _Pragma("unroll")                                                      \
        for (int rr = 0; rr < 4; ++rr)                                         \
            *(uint4*)&As[(sr + rr * 32) * 36 + si] = av[rr];                   \
        _Pragma("unroll")                                                      \
        for (int ii = 0; ii < 4; ++ii)                                         \
            *(uint4*)&Bs[sr * 136 + si + ii * 32] = bv[ii];                    \
        __syncthreads();                                                       \
        _Pragma("unroll")                                                      \
        for (int c = 0; c < 4; ++c) {                                          \
            uint32_t afr[4][4], bfr[4][2];                                     \
            _Pragma("unroll")                                                  \
            for (int mf = 0; mf < 4; ++mf) {                                   \
                const int m = wm + mf * 16 + gid;                              \
                afr[mf][0] = As[m * 36 + c * 8 + tg];                          \
                afr[mf][1] = As[(m + 8) * 36 + c * 8 + tg];                    \
                afr[mf][2] = As[m * 36 + c * 8 + tg + 4];                      \
                afr[mf][3] = As[(m + 8) * 36 + c * 8 + tg + 4];                \
            }                                                                  \
            _Pragma("unroll")                                                  \
            for (int nf = 0; nf < 4; ++nf) {                                   \
                const int n = wn + nf * 8 + gid;                               \
                bfr[nf][0] = Bs[(c * 8 + tg) * 136 + n];                       \
                bfr[nf][1] = Bs[(c * 8 + tg + 4) * 136 + n];                   \
            }                                                                  \
            _Pragma("unroll")                                                  \
            for (int mf = 0; mf < 4; ++mf)                                     \
                _Pragma("unroll")                                              \
                for (int nf = 0; nf < 4; ++nf)                                 \
                    mma_f16(acc[mf][nf], afr[mf], bfr[nf]);                    \
        }                                                                      \
    }

// qkv projection: grid (24, 64). Writes q/k/v as fp16 (q pre-scaled 0.125).
__global__ __launch_bounds__(256) void qkv_gemm_kernel(const float* __restrict__ bias)
{
    const int ng = blockIdx.x * 128;
    const int m0 = blockIdx.y * 128;
    const uint32_t* Ag = (ng < 1024) ? b_inq : b_inx;
    GEMM_MAIN(Ag, b_w2, 3072)

    uint32_t* Og; int ccol; float scale;
    if (ng < 1024)       { Og = b_q; ccol = ng;        scale = 0.125f; }
    else if (ng < 2048)  { Og = b_k; ccol = ng - 1024; scale = 1.0f; }
    else                 { Og = b_v; ccol = ng - 2048; scale = 1.0f; }

#pragma unroll
    for (int nf = 0; nf < 4; ++nf) {
        const int cl = wn + nf * 8 + 2 * tg;
        const float b0 = bias[ng + cl], b1 = bias[ng + cl + 1];
#pragma unroll
        for (int mf = 0; mf < 4; ++mf) {
            const int row = m0 + wm + mf * 16 + gid;
            Og[(size_t)row * 512 + (ccol + cl) / 2] =
                pack_h2((acc[mf][nf][0] + b0) * scale,
                        (acc[mf][nf][1] + b1) * scale);
            Og[(size_t)(row + 8) * 512 + (ccol + cl) / 2] =
                pack_h2((acc[mf][nf][2] + b0) * scale,
                        (acc[mf][nf][3] + b1) * scale);
        }
    }
}

// output projection: grid (8, 64). Reads b_a (fp16), writes f32 out.
__global__ __launch_bounds__(256) void proj_gemm_kernel(
    const float* __restrict__ bias, float* __restrict__ out)
{
    const int ng = blockIdx.x * 128;
    const int m0 = blockIdx.y * 128;
    const uint32_t* Ag = b_a;
    GEMM_MAIN(Ag, b_p2, 1024)

#pragma unroll
    for (int nf = 0; nf < 4; ++nf) {
        const int cl = wn + nf * 8 + 2 * tg;
        const float b0 = bias[ng + cl], b1 = bias[ng + cl + 1];
#pragma unroll
        for (int mf = 0; mf < 4; ++mf) {
            const int row = m0 + wm + mf * 16 + gid;
            *(float2*)(out + (size_t)row * 1024 + ng + cl) =
                make_float2(acc[mf][nf][0] + b0, acc[mf][nf][1] + b1);
            *(float2*)(out + (size_t)(row + 8) * 1024 + ng + cl) =
                make_float2(acc[mf][nf][2] + b0, acc[mf][nf][3] + b1);
        }
    }
}

// ---------------------------------------------------------------------------
// fp16 flash attention. Grid (8, 16, 8), 256 thr (8 warps x 16 q-rows).
// Qs[m][d] halves (pitch 36 words); Ks[d2][key] pairs-of-d (pitch 72);
// Vs[key2][d] pairs-of-keys (pitch 72). P stays in registers.
// ---------------------------------------------------------------------------
__global__ __launch_bounds__(256) void attn_kernel()
{
    __shared__ __align__(16) uint32_t Qs[128 * 36];
    __shared__ __align__(16) uint32_t Ks[32 * 72];
    __shared__ __align__(16) uint32_t Vs[32 * 72];

    const int qb = blockIdx.x, h = blockIdx.y, b = blockIdx.z;
    const int t = threadIdx.x;
    const int warp = t >> 5, lane = t & 31;
    const int gid = lane >> 2, tg = lane & 3;
    const int r0 = warp * 16 + gid, r1 = r0 + 8;
    const size_t qrow0 = (size_t)(b * SEQ + qb * 128);

    // stage Q (already scaled by 0.125 in qkv epilogue)
    {
        const int sr = t >> 3, si = (t & 7) * 4;
#pragma unroll
        for (int rr = 0; rr < 4; ++rr) {
            uint4 v = *(const uint4*)(b_q + (qrow0 + sr + rr * 32) * 512
                                      + h * 32 + si);
            *(uint4*)&Qs[(sr + rr * 32) * 36 + si] = v;
        }
    }
    __syncthreads();

    uint32_t qf[4][4];
#pragma unroll
    for (int c = 0; c < 4; ++c) {
        qf[c][0] = Qs[r0 * 36 + c * 8 + tg];
        qf[c][1] = Qs[r1 * 36 + c * 8 + tg];
        qf[c][2] = Qs[r0 * 36 + c * 8 + tg + 4];
        qf[c][3] = Qs[r1 * 36 + c * 8 + tg + 4];
    }

    float m_i[2] = {-3.0e38f, -3.0e38f};
    float l_i[2] = {0.0f, 0.0f};
    float O[8][4];
#pragma unroll
    for (int nf = 0; nf < 8; ++nf)
#pragma unroll
        for (int r = 0; r < 4; ++r) O[nf][r] = 0.0f;

    const int nkb = 2 * qb + 2;

    for (int kb = 0; kb < nkb; ++kb) {
        __syncthreads();

        // stage K: Ks[d2][key]
        {
            const int key = t & 63;
            const int wg = (t >> 6) * 8;
            const uint32_t* kp = b_k + ((size_t)(b * SEQ + kb * 64 + key)) * 512
                                 + h * 32 + wg;
            uint4 k0 = *(const uint4*)kp;
            uint4 k1 = *(const uint4*)(kp + 4);
            Ks[(wg + 0) * 72 + key] = k0.x; Ks[(wg + 1) * 72 + key] = k0.y;
            Ks[(wg + 2) * 72 + key] = k0.z; Ks[(wg + 3) * 72 + key] = k0.w;
            Ks[(wg + 4) * 72 + key] = k1.x; Ks[(wg + 5) * 72 + key] = k1.y;
            Ks[(wg + 6) * 72 + key] = k1.z; Ks[(wg + 7) * 72 + key] = k1.w;
        }
        // stage V: Vs[key2][d] = (V[2k2][d], V[2k2+1][d])
        {
            const int k2 = t >> 3;
            const int dw = (t & 7) * 4;
            const uint32_t* ve = b_v + ((size_t)(b * SEQ + kb * 64 + 2 * k2)) * 512
                                 + h * 32 + dw;
            uint4 e = *(const uint4*)ve;
            uint4 o = *(const uint4*)(ve + 512);
            uint32_t* vd = &Vs[k2 * 72 + 2 * dw];
            vd[0] = prmt(e.x, o.x, 0x5410); vd[1] = prmt(e.x, o.x, 0x7632);
            vd[2] = prmt(e.y, o.y, 0x5410); vd[3] = prmt(e.y, o.y, 0x7632);
            vd[4] = prmt(e.z, o.z, 0x5410); vd[5] = prmt(e.z, o.z, 0x7632);
            vd[6] = prmt(e.w, o.w, 0x5410); vd[7] = prmt(e.w, o.w, 0x7632);
        }
        __syncthreads();

        // S = Q K^T
        float s[8][4];
#pragma unroll
        for (int nf = 0; nf < 8; ++nf)
#pragma unroll
            for (int r = 0; r < 4; ++r) s[nf][r] = 0.0f;
#pragma unroll
        for (int c = 0; c < 4; ++c)
#pragma unroll
            for (int nf = 0; nf < 8; ++nf) {
                uint32_t bb[2];
                bb[0] = Ks[(c * 8 + tg) * 72 + nf * 8 + gid];
                bb[1] = Ks[(c * 8 + tg + 4) * 72 + nf * 8 + gid];
                mma_f16(s[nf], qf[c], bb);
            }

        // causal mask
        if (kb >= 2 * qb) {
            const int grow0 = qb * 128 + r0;
            const int gcol0 = kb * 64 + 2 * tg;
#pragma unroll
            for (int nf = 0; nf < 8; ++nf) {
                int c = gcol0 + nf * 8;
                if (c     > grow0)     s[nf][0] = -10000.0f;
                if (c + 1 > grow0)     s[nf][1] = -10000.0f;
                if (c     > grow0 + 8) s[nf][2] = -10000.0f;
                if (c + 1 > grow0 + 8) s[nf][3] = -10000.0f;
            }
        }

        // online softmax
        float rm0 = s[0][0], rm1 = s[0][2];
#pragma unroll
        for (int nf = 0; nf < 8; ++nf) {
            rm0 = fmaxf(rm0, fmaxf(s[nf][0], s[nf][1]));
            rm1 = fmaxf(rm1, fmaxf(s[nf][2], s[nf][3]));
        }
        rm0 = fmaxf(rm0, __shfl_xor_sync(0xffffffffu, rm0, 1));
        rm0 = fmaxf(rm0, __shfl_xor_sync(0xffffffffu, rm0, 2));
        rm1 = fmaxf(rm1, __shfl_xor_sync(0xffffffffu, rm1, 1));
        rm1 = fmaxf(rm1, __shfl_xor_sync(0xffffffffu, rm1, 2));

        const float mn0 = fmaxf(m_i[0], rm0);
        const float mn1 = fmaxf(m_i[1], rm1);
        const float alpha0 = __expf(m_i[0] - mn0);
        const float alpha1 = __expf(m_i[1] - mn1);
        m_i[0] = mn0; m_i[1] = mn1;

        float ls0 = 0.0f, ls1 = 0.0f;
        uint32_t ph0[8], ph1[8];
#pragma unroll
        for (int nf = 0; nf < 8; ++nf) {
            float p0 = __expf(s[nf][0] - mn0);
            float p1 = __expf(s[nf][1] - mn0);
            float p2 = __expf(s[nf][2] - mn1);
            float p3 = __expf(s[nf][3] - mn1);
            ls0 += p0 + p1;
            ls1 += p2 + p3;
            ph0[nf] = pack_h2(p0, p1);
            ph1[nf] = pack_h2(p2, p3);
        }
        ls0 += __shfl_xor_sync(0xffffffffu, ls0, 1);
        ls0 += __shfl_xor_sync(0xffffffffu, ls0, 2);
        ls1 += __shfl_xor_sync(0xffffffffu, ls1, 1);
        ls1 += __shfl_xor_sync(0xffffffffu, ls1, 2);

        l_i[0] = l_i[0] * alpha0 + ls0;
        l_i[1] = l_i[1] * alpha1 + ls1;
#pragma unroll
        for (int nf = 0; nf < 8; ++nf) {
            O[nf][0] *= alpha0; O[nf][1] *= alpha0;
            O[nf][2] *= alpha1; O[nf][3] *= alpha1;
        }

        // O += P V  (P fragments live in registers)
#pragma unroll
        for (int c = 0; c < 4; ++c) {
            uint32_t af[4] = {ph0[2 * c], ph1[2 * c], ph0[2 * c + 1], ph1[2 * c + 1]};
#pragma unroll
            for (int nf = 0; nf < 8; ++nf) {
                uint32_t bb[2];
                bb[0] = Vs[(c * 8 + tg) * 72 + nf * 8 + gid];
                bb[1] = Vs[(c * 8 + tg + 4) * 72 + nf * 8 + gid];
                mma_f16(O[nf], af, bb);
            }
        }
    }

    // normalize, write fp16 merged-head output
    const float inv0 = 1.0f / l_i[0];
    const float inv1 = 1.0f / l_i[1];
#pragma unroll
    for (int nf = 0; nf < 8; ++nf) {
        b_a[(qrow0 + r0) * 512 + h * 32 + nf * 4 + tg] =
            pack_h2(O[nf][0] * inv0, O[nf][1] * inv0);
        b_a[(qrow0 + r1) * 512 + h * 32 + nf * 4 + tg] =
            pack_h2(O[nf][2] * inv1, O[nf][3] * inv1);
    }
}

// ---------------------------------------------------------------------------
// Launch
// ---------------------------------------------------------------------------
extern "C" void kernel_launch(void* const* d_in, const int* in_sizes, int n_in,
                              void* d_out, int out_size)
{
    const float* x     = (const float*)d_in[0];
    const float* query = (const float*)d_in[1];
    const float* attw  = (const float*)d_in[2];
    const float* attb  = (const float*)d_in[3];
    const float* projw = (const float*)d_in[4];
    const float* projb = (const float*)d_in[5];
    float* out = (float*)d_out;

    uint32_t *w2_, *p2_;
    cudaGetSymbolAddress((void**)&w2_, b_w2);
    cudaGetSymbolAddress((void**)&p2_, b_p2);

    // pre-passes: fp16 conversion + weight transpose-pack
    cvt_f16_kernel<<<dim3(8192, 2), 256>>>((const float4*)query, (const float4*)x);
    packw_kernel<<<dim3(3, 512), 256>>>(attw, 3 * NX, w2_);
    packw_kernel<<<dim3(1, 512), 256>>>(projw, NX, p2_);

    // q/k/v projections
    qkv_gemm_kernel<<<dim3(24, 64), 256>>>(attb);

    // attention
    attn_kernel<<<dim3(8, NH, BSZ), 256>>>();

    // output projection
    proj_gemm_kernel<<<dim3(8, 64), 256>>>(projb, out);
}

// round 7
// speedup vs baseline: 1.8234x; 1.0517x over previous
#include <cuda_runtime.h>
#include <cuda_fp16.h>
#include <cstdint>

// Problem constants
#define BSZ 8
#define SEQ 1024
#define NX  1024
#define NH  16
#define HD  64

// All half-precision buffers stored as uint32 words (2 halves per word)
__device__ uint32_t b_inq[8192 * 512];   // query, fp16
__device__ uint32_t b_inx[8192 * 512];   // x, fp16
__device__ uint32_t b_w2[512 * 3072];    // attw packed: [k2][n], word=(k even, k odd)
__device__ uint32_t b_p2[512 * 1024];    // projw packed
__device__ uint32_t b_q[8192 * 512];     // q*0.125, fp16
__device__ uint32_t b_k[8192 * 512];
__device__ uint32_t b_v[8192 * 512];
__device__ uint32_t b_a[8192 * 512];     // attention out, fp16

// ---------------------------------------------------------------------------
// helpers
// ---------------------------------------------------------------------------
__device__ __forceinline__ uint32_t pack_h2(float lo, float hi) {
    uint32_t d;
    asm("cvt.rn.f16x2.f32 %0, %1, %2;" : "=r"(d) : "f"(hi), "f"(lo));
    return d;
}
__device__ __forceinline__ uint32_t prmt(uint32_t a, uint32_t b, uint32_t sel) {
    uint32_t d;
    asm("prmt.b32 %0, %1, %2, %3;" : "=r"(d) : "r"(a), "r"(b), "r"(sel));
    return d;
}
__device__ __forceinline__ void mma_f16(float c[4], const uint32_t a[4],
                                        const uint32_t b[2]) {
    asm volatile(
        "mma.sync.aligned.m16n8k16.row.col.f32.f16.f16.f32 "
        "{%0,%1,%2,%3}, {%4,%5,%6,%7}, {%8,%9}, {%0,%1,%2,%3};\n"
        : "+f"(c[0]), "+f"(c[1]), "+f"(c[2]), "+f"(c[3])
        : "r"(a[0]), "r"(a[1]), "r"(a[2]), "r"(a[3]), "r"(b[0]), "r"(b[1]));
}
__device__ __forceinline__ void ldmatrix_x4(uint32_t r[4], uint32_t addr) {
    asm volatile("ldmatrix.sync.aligned.m8n8.x4.shared.b16 {%0,%1,%2,%3}, [%4];"
                 : "=r"(r[0]), "=r"(r[1]), "=r"(r[2]), "=r"(r[3]) : "r"(addr));
}
__device__ __forceinline__ void cpa16(uint32_t dst, const void* src) {
    asm volatile("cp.async.cg.shared.global [%0], [%1], 16;" :: "r"(dst), "l"(src));
}
__device__ __forceinline__ uint32_t smem_u32(const void* p) {
    uint32_t a;
    asm("{ .reg .u64 t; cvta.to.shared.u64 t, %1; cvt.u32.u64 %0, t; }"
        : "=r"(a) : "l"(p));
    return a;
}

// ---------------------------------------------------------------------------
// pre-passes
// ---------------------------------------------------------------------------
__global__ __launch_bounds__(256) void cvt_f16_kernel(
    const float4* __restrict__ q, const float4* __restrict__ x)
{
    const size_t i = (size_t)blockIdx.x * 256 + threadIdx.x;
    const float4 f = (blockIdx.y == 0) ? q[i] : x[i];
    uint32_t* o = (blockIdx.y == 0) ? b_inq : b_inx;
    o[2 * i]     = pack_h2(f.x, f.y);
    o[2 * i + 1] = pack_h2(f.z, f.w);
}

// W [1024][N] f32 -> out [512][N] words, word n = (W[2k2][n], W[2k2+1][n])
__global__ __launch_bounds__(256) void packw_kernel(
    const float* __restrict__ W, int N, uint32_t* __restrict__ out)
{
    const int n4 = blockIdx.x * 256 + threadIdx.x;
    const int k2 = blockIdx.y;
    const float4 e = *(const float4*)(W + (size_t)(2 * k2) * N + 4 * n4);
    const float4 o = *(const float4*)(W + (size_t)(2 * k2 + 1) * N + 4 * n4);
    uint4 r;
    r.x = pack_h2(e.x, o.x); r.y = pack_h2(e.y, o.y);
    r.z = pack_h2(e.z, o.z); r.w = pack_h2(e.w, o.w);
    *(uint4*)(out + (size_t)k2 * N + 4 * n4) = r;
}

// ---------------------------------------------------------------------------
// fp16 GEMM mainloop: CTA 128x128, 256 thr = 8 warps (2m x 4n), warp 64x32.
// cp.async double-buffered (2 stages), ldmatrix.x4 A fragments.
// As[m] pitch 36 words (64 halves + pad); Bs[k2] pitch 136 words.
// ---------------------------------------------------------------------------
#define AW 36
#define BW 136
#define STW (128 * AW + 32 * BW)          // words per stage = 8960
#define GEMM_DYN (2 * STW * 4)            // 71680 bytes

__device__ __forceinline__ void gemm16_main(
    const uint32_t* __restrict__ Ag, const uint32_t* __restrict__ Wg,
    int ldw2, int m0, int ng, float acc[4][4][4])
{
    extern __shared__ __align__(16) uint32_t smw[];
    const uint32_t sbase = smem_u32(smw);

    const int t = threadIdx.x;
    const int lane = t & 31;
    const int warp = t >> 5;
    const int gid = lane >> 2, tg = lane & 3;
    const int wm = (warp & 1) * 64, wn = (warp >> 1) * 32;
    const int sr = t >> 3;
    const int si = (t & 7) * 4;

#pragma unroll
    for (int i = 0; i < 4; ++i)
#pragma unroll
        for (int j = 0; j < 4; ++j)
#pragma unroll
            for (int r = 0; r < 4; ++r) acc[i][j][r] = 0.0f;

    // stage loader: A rows sr+32rr words kt*32+si.. ; B rows kt*32+sr cols si+32ii
    auto load_stage = [&](int kt, int st) {
        const uint32_t sa = sbase + (st * STW) * 4;
        const uint32_t sb = sa + (128 * AW) * 4;
#pragma unroll
        for (int rr = 0; rr < 4; ++rr)
            cpa16(sa + ((sr + rr * 32) * AW + si) * 4,
                  Ag + (size_t)(m0 + sr + rr * 32) * 512 + kt * 32 + si);
#pragma unroll
        for (int ii = 0; ii < 4; ++ii)
            cpa16(sb + (sr * BW + si + ii * 32) * 4,
                  Wg + (size_t)(kt * 32 + sr) * ldw2 + ng + si + ii * 32);
        asm volatile("cp.async.commit_group;" ::: "memory");
    };

    load_stage(0, 0);

    for (int kt = 0; kt < 16; ++kt) {
        const int cur = kt & 1;
        asm volatile("cp.async.wait_group 0;" ::: "memory");
        __syncthreads();
        if (kt + 1 < 16) load_stage(kt + 1, cur ^ 1);

        const uint32_t sa = sbase + (cur * STW) * 4;
        const uint32_t* Bs = smw + cur * STW + 128 * AW;
        const uint32_t arow = (uint32_t)(lane & 15);
        const uint32_t ahalf = (uint32_t)(lane >> 4) * 4;

#pragma unroll
        for (int c = 0; c < 4; ++c) {
            uint32_t afr[4][4], bfr[4][2];
#pragma unroll
            for (int mf = 0; mf < 4; ++mf)
                ldmatrix_x4(afr[mf],
                    sa + ((wm + mf * 16 + arow) * AW + c * 8 + ahalf) * 4);
#pragma unroll
            for (int nf = 0; nf < 4; ++nf) {
                const int n = wn + nf * 8 + gid;
                bfr[nf][0] = Bs[(c * 8 + tg) * BW + n];
                bfr[nf][1] = Bs[(c * 8 + tg + 4) * BW + n];
            }
#pragma unroll
            for (int mf = 0; mf < 4; ++mf)
#pragma unroll
                for (int nf = 0; nf < 4; ++nf)
                    mma_f16(acc[mf][nf], afr[mf], bfr[nf]);
        }
    }
}

// qkv projection: grid (24, 64). Writes q/k/v as fp16 (q pre-scaled 0.125).
__global__ __launch_bounds__(256) void qkv_gemm_kernel(const float* __restrict__ bias)
{
    const int ng = blockIdx.x * 128;
    const int m0 = blockIdx.y * 128;
    const uint32_t* Ag = (ng < 1024) ? b_inq : b_inx;
    float acc[4][4][4];
    gemm16_main(Ag, b_w2, 3072, m0, ng, acc);

    const int t = threadIdx.x;
    const int lane = t & 31, warp = t >> 5;
    const int gid = lane >> 2, tg = lane & 3;
    const int wm = (warp & 1) * 64, wn = (warp >> 1) * 32;

    uint32_t* Og; int ccol; float scale;
    if (ng < 1024)       { Og = b_q; ccol = ng;        scale = 0.125f; }
    else if (ng < 2048)  { Og = b_k; ccol = ng - 1024; scale = 1.0f; }
    else                 { Og = b_v; ccol = ng - 2048; scale = 1.0f; }

#pragma unroll
    for (int nf = 0; nf < 4; ++nf) {
        const int cl = wn + nf * 8 + 2 * tg;
        const float b0 = bias[ng + cl], b1 = bias[ng + cl + 1];
#pragma unroll
        for (int mf = 0; mf < 4; ++mf) {
            const int row = m0 + wm + mf * 16 + gid;
            Og[(size_t)row * 512 + (ccol + cl) / 2] =
                pack_h2((acc[mf][nf][0] + b0) * scale,
                        (acc[mf][nf][1] + b1) * scale);
            Og[(size_t)(row + 8) * 512 + (ccol + cl) / 2] =
                pack_h2((acc[mf][nf][2] + b0) * scale,
                        (acc[mf][nf][3] + b1) * scale);
        }
    }
}

// output projection: grid (8, 64). Reads b_a (fp16), writes f32 out.
__global__ __launch_bounds__(256) void proj_gemm_kernel(
    const float* __restrict__ bias, float* __restrict__ out)
{
    const int ng = blockIdx.x * 128;
    const int m0 = blockIdx.y * 128;
    float acc[4][4][4];
    gemm16_main(b_a, b_p2, 1024, m0, ng, acc);

    const int t = threadIdx.x;
    const int lane = t & 31, warp = t >> 5;
    const int gid = lane >> 2, tg = lane & 3;
    const int wm = (warp & 1) * 64, wn = (warp >> 1) * 32;

#pragma unroll
    for (int nf = 0; nf < 4; ++nf) {
        const int cl = wn + nf * 8 + 2 * tg;
        const float b0 = bias[ng + cl], b1 = bias[ng + cl + 1];
#pragma unroll
        for (int mf = 0; mf < 4; ++mf) {
            const int row = m0 + wm + mf * 16 + gid;
            *(float2*)(out + (size_t)row * 1024 + ng + cl) =
                make_float2(acc[mf][nf][0] + b0, acc[mf][nf][1] + b1);
            *(float2*)(out + (size_t)(row + 8) * 1024 + ng + cl) =
                make_float2(acc[mf][nf][2] + b0, acc[mf][nf][3] + b1);
        }
    }
}

// ---------------------------------------------------------------------------
// fp16 flash attention (unchanged from R6). Grid (8, 16, 8), 256 thr.
// ---------------------------------------------------------------------------
__global__ __launch_bounds__(256) void attn_kernel()
{
    __shared__ __align__(16) uint32_t Qs[128 * 36];
    __shared__ __align__(16) uint32_t Ks[32 * 72];
    __shared__ __align__(16) uint32_t Vs[32 * 72];

    const int qb = blockIdx.x, h = blockIdx.y, b = blockIdx.z;
    const int t = threadIdx.x;
    const int warp = t >> 5, lane = t & 31;
    const int gid = lane >> 2, tg = lane & 3;
    const int r0 = warp * 16 + gid, r1 = r0 + 8;
    const size_t qrow0 = (size_t)(b * SEQ + qb * 128);

    {
        const int sr = t >> 3, si = (t & 7) * 4;
#pragma unroll
        for (int rr = 0; rr < 4; ++rr) {
            uint4 v = *(const uint4*)(b_q + (qrow0 + sr + rr * 32) * 512
                                      + h * 32 + si);
            *(uint4*)&Qs[(sr + rr * 32) * 36 + si] = v;
        }
    }
    __syncthreads();

    uint32_t qf[4][4];
#pragma unroll
    for (int c = 0; c < 4; ++c) {
        qf[c][0] = Qs[r0 * 36 + c * 8 + tg];
        qf[c][1] = Qs[r1 * 36 + c * 8 + tg];
        qf[c][2] = Qs[r0 * 36 + c * 8 + tg + 4];
        qf[c][3] = Qs[r1 * 36 + c * 8 + tg + 4];
    }

    float m_i[2] = {-3.0e38f, -3.0e38f};
    float l_i[2] = {0.0f, 0.0f};
    float O[8][4];
#pragma unroll
    for (int nf = 0; nf < 8; ++nf)
#pragma unroll
        for (int r = 0; r < 4; ++r) O[nf][r] = 0.0f;

    const int nkb = 2 * qb + 2;

    for (int kb = 0; kb < nkb; ++kb) {
        __syncthreads();
        {
            const int key = t & 63;
            const int wg = (t >> 6) * 8;
            const uint32_t* kp = b_k + ((size_t)(b * SEQ + kb * 64 + key)) * 512
                                 + h * 32 + wg;
            uint4 k0 = *(const uint4*)kp;
            uint4 k1 = *(const uint4*)(kp + 4);
            Ks[(wg + 0) * 72 + key] = k0.x; Ks[(wg + 1) * 72 + key] = k0.y;
            Ks[(wg + 2) * 72 + key] = k0.z; Ks[(wg + 3) * 72 + key] = k0.w;
            Ks[(wg + 4) * 72 + key] = k1.x; Ks[(wg + 5) * 72 + key] = k1.y;
            Ks[(wg + 6) * 72 + key] = k1.z; Ks[(wg + 7) * 72 + key] = k1.w;
        }
        {
            const int k2 = t >> 3;
            const int dw = (t & 7) * 4;
            const uint32_t* ve = b_v + ((size_t)(b * SEQ + kb * 64 + 2 * k2)) * 512
                                 + h * 32 + dw;
            uint4 e = *(const uint4*)ve;
            uint4 o = *(const uint4*)(ve + 512);
            uint32_t* vd = &Vs[k2 * 72 + 2 * dw];
            vd[0] = prmt(e.x, o.x, 0x5410); vd[1] = prmt(e.x, o.x, 0x7632);
            vd[2] = prmt(e.y, o.y, 0x5410); vd[3] = prmt(e.y, o.y, 0x7632);
            vd[4] = prmt(e.z, o.z, 0x5410); vd[5] = prmt(e.z, o.z, 0x7632);
            vd[6] = prmt(e.w, o.w, 0x5410); vd[7] = prmt(e.w, o.w, 0x7632);
        }
        __syncthreads();

        float s[8][4];
#pragma unroll
        for (int nf = 0; nf < 8; ++nf)
#pragma unroll
            for (int r = 0; r < 4; ++r) s[nf][r] = 0.0f;
#pragma unroll
        for (int c = 0; c < 4; ++c)
#pragma unroll
            for (int nf = 0; nf < 8; ++nf) {
                uint32_t bb[2];
                bb[0] = Ks[(c * 8 + tg) * 72 + nf * 8 + gid];
                bb[1] = Ks[(c * 8 + tg + 4) * 72 + nf * 8 + gid];
                mma_f16(s[nf], qf[c], bb);
            }

        if (kb >= 2 * qb) {
            const int grow0 = qb * 128 + r0;
            const int gcol0 = kb * 64 + 2 * tg;
#pragma unroll
            for (int nf = 0; nf < 8; ++nf) {
                int c = gcol0 + nf * 8;
                if (c     > grow0)     s[nf][0] = -10000.0f;
                if (c + 1 > grow0)     s[nf][1] = -10000.0f;
                if (c     > grow0 + 8) s[nf][2] = -10000.0f;
                if (c + 1 > grow0 + 8) s[nf][3] = -10000.0f;
            }
        }

        float rm0 = s[0][0], rm1 = s[0][2];
#pragma unroll
        for (int nf = 0; nf < 8; ++nf) {
            rm0 = fmaxf(rm0, fmaxf(s[nf][0], s[nf][1]));
            rm1 = fmaxf(rm1, fmaxf(s[nf][2], s[nf][3]));
        }
        rm0 = fmaxf(rm0, __shfl_xor_sync(0xffffffffu, rm0, 1));
        rm0 = fmaxf(rm0, __shfl_xor_sync(0xffffffffu, rm0, 2));
        rm1 = fmaxf(rm1, __shfl_xor_sync(0xffffffffu, rm1, 1));
        rm1 = fmaxf(rm1, __shfl_xor_sync(0xffffffffu, rm1, 2));

        const float mn0 = fmaxf(m_i[0], rm0);
        const float mn1 = fmaxf(m_i[1], rm1);
        const float alpha0 = __expf(m_i[0] - mn0);
        const float alpha1 = __expf(m_i[1] - mn1);
        m_i[0] = mn0; m_i[1] = mn1;

        float ls0 = 0.0f, ls1 = 0.0f;
        uint32_t ph0[8], ph1[8];
#pragma unroll
        for (int nf = 0; nf < 8; ++nf) {
            float p0 = __expf(s[nf][0] - mn0);
            float p1 = __expf(s[nf][1] - mn0);
            float p2 = __expf(s[nf][2] - mn1);
            float p3 = __expf(s[nf][3] - mn1);
            ls0 += p0 + p1;
            ls1 += p2 + p3;
            ph0[nf] = pack_h2(p0, p1);
            ph1[nf] = pack_h2(p2, p3);
        }
        ls0 += __shfl_xor_sync(0xffffffffu, ls0, 1);
        ls0 += __shfl_xor_sync(0xffffffffu, ls0, 2);
        ls1 += __shfl_xor_sync(0xffffffffu, ls1, 1);
        ls1 += __shfl_xor_sync(0xffffffffu, ls1, 2);

        l_i[0] = l_i[0] * alpha0 + ls0;
        l_i[1] = l_i[1] * alpha1 + ls1;
#pragma unroll
        for (int nf = 0; nf < 8; ++nf) {
            O[nf][0] *= alpha0; O[nf][1] *= alpha0;
            O[nf][2] *= alpha1; O[nf][3] *= alpha1;
        }

#pragma unroll
        for (int c = 0; c < 4; ++c) {
            uint32_t af[4] = {ph0[2 * c], ph1[2 * c], ph0[2 * c + 1], ph1[2 * c + 1]};
#pragma unroll
            for (int nf = 0; nf < 8; ++nf) {
                uint32_t bb[2];
                bb[0] = Vs[(c * 8 + tg) * 72 + nf * 8 + gid];
                bb[1] = Vs[(c * 8 + tg + 4) * 72 + nf * 8 + gid];
                mma_f16(O[nf], af, bb);
            }
        }
    }

    const float inv0 = 1.0f / l_i[0];
    const float inv1 = 1.0f / l_i[1];
#pragma unroll
    for (int nf = 0; nf < 8; ++nf) {
        b_a[(qrow0 + r0) * 512 + h * 32 + nf * 4 + tg] =
            pack_h2(O[nf][0] * inv0, O[nf][1] * inv0);
        b_a[(qrow0 + r1) * 512 + h * 32 + nf * 4 + tg] =
            pack_h2(O[nf][2] * inv1, O[nf][3] * inv1);
    }
}

// ---------------------------------------------------------------------------
// Launch
// ---------------------------------------------------------------------------
extern "C" void kernel_launch(void* const* d_in, const int* in_sizes, int n_in,
                              void* d_out, int out_size)
{
    const float* x     = (const float*)d_in[0];
    const float* query = (const float*)d_in[1];
    const float* attw  = (const float*)d_in[2];
    const float* attb  = (const float*)d_in[3];
    const float* projw = (const float*)d_in[4];
    const float* projb = (const float*)d_in[5];
    float* out = (float*)d_out;

    uint32_t *w2_, *p2_;
    cudaGetSymbolAddress((void**)&w2_, b_w2);
    cudaGetSymbolAddress((void**)&p2_, b_p2);

    cudaFuncSetAttribute(qkv_gemm_kernel,
                         cudaFuncAttributeMaxDynamicSharedMemorySize, GEMM_DYN);
    cudaFuncSetAttribute(proj_gemm_kernel,
                         cudaFuncAttributeMaxDynamicSharedMemorySize, GEMM_DYN);

    // pre-passes: fp16 conversion + weight transpose-pack
    cvt_f16_kernel<<<dim3(8192, 2), 256>>>((const float4*)query, (const float4*)x);
    packw_kernel<<<dim3(3, 512), 256>>>(attw, 3 * NX, w2_);
    packw_kernel<<<dim3(1, 512), 256>>>(projw, NX, p2_);

    // q/k/v projections
    qkv_gemm_kernel<<<dim3(24, 64), 256, GEMM_DYN>>>(attb);

    // attention
    attn_kernel<<<dim3(8, NH, BSZ), 256>>>();

    // output projection
    proj_gemm_kernel<<<dim3(8, 64), 256, GEMM_DYN>>>(projb, out);
}

// round 8
// speedup vs baseline: 2.8914x; 1.5857x over previous
#include <cuda_runtime.h>
#include <cuda_fp16.h>
#include <cstdint>

// Problem constants
#define BSZ 8
#define SEQ 1024
#define NX  1024
#define NH  16
#define HD  64

// All half-precision buffers stored as uint32 words (2 halves per word)
__device__ uint32_t b_inq[8192 * 512];   // query, fp16
__device__ uint32_t b_inx[8192 * 512];   // x, fp16
__device__ uint32_t b_w2[512 * 3072];    // attw packed: [k2][n], word=(k even, k odd)
__device__ uint32_t b_p2[512 * 1024];    // projw packed
__device__ uint32_t b_q[8192 * 512];     // q*0.125, fp16
__device__ uint32_t b_k[8192 * 512];
__device__ uint32_t b_v[8192 * 512];
__device__ uint32_t b_a[8192 * 512];     // attention out, fp16

// ---------------------------------------------------------------------------
// helpers
// ---------------------------------------------------------------------------
__device__ __forceinline__ uint32_t pack_h2(float lo, float hi) {
    uint32_t d;
    asm("cvt.rn.f16x2.f32 %0, %1, %2;" : "=r"(d) : "f"(hi), "f"(lo));
    return d;
}
__device__ __forceinline__ void mma_f16(float c[4], const uint32_t a[4],
                                        const uint32_t b[2]) {
    asm volatile(
        "mma.sync.aligned.m16n8k16.row.col.f32.f16.f16.f32 "
        "{%0,%1,%2,%3}, {%4,%5,%6,%7}, {%8,%9}, {%0,%1,%2,%3};\n"
        : "+f"(c[0]), "+f"(c[1]), "+f"(c[2]), "+f"(c[3])
        : "r"(a[0]), "r"(a[1]), "r"(a[2]), "r"(a[3]), "r"(b[0]), "r"(b[1]));
}
__device__ __forceinline__ void ldmatrix_x4(uint32_t r[4], uint32_t addr) {
    asm volatile("ldmatrix.sync.aligned.m8n8.x4.shared.b16 {%0,%1,%2,%3}, [%4];"
                 : "=r"(r[0]), "=r"(r[1]), "=r"(r[2]), "=r"(r[3]) : "r"(addr));
}
__device__ __forceinline__ void ldmatrix_x4t(uint32_t r[4], uint32_t addr) {
    asm volatile("ldmatrix.sync.aligned.m8n8.x4.trans.shared.b16 {%0,%1,%2,%3}, [%4];"
                 : "=r"(r[0]), "=r"(r[1]), "=r"(r[2]), "=r"(r[3]) : "r"(addr));
}
__device__ __forceinline__ void cpa16(uint32_t dst, const void* src) {
    asm volatile("cp.async.cg.shared.global [%0], [%1], 16;" :: "r"(dst), "l"(src));
}
__device__ __forceinline__ uint32_t smem_u32(const void* p) {
    uint32_t a;
    asm("{ .reg .u64 t; cvta.to.shared.u64 t, %1; cvt.u32.u64 %0, t; }"
        : "=r"(a) : "l"(p));
    return a;
}

// ---------------------------------------------------------------------------
// pre-passes
// ---------------------------------------------------------------------------
__global__ __launch_bounds__(256) void cvt_f16_kernel(
    const float4* __restrict__ q, const float4* __restrict__ x)
{
    const size_t i = (size_t)blockIdx.x * 256 + threadIdx.x;
    const float4 f = (blockIdx.y == 0) ? q[i] : x[i];
    uint32_t* o = (blockIdx.y == 0) ? b_inq : b_inx;
    o[2 * i]     = pack_h2(f.x, f.y);
    o[2 * i + 1] = pack_h2(f.z, f.w);
}

// W [1024][N] f32 -> out [512][N] words, word n = (W[2k2][n], W[2k2+1][n])
__global__ __launch_bounds__(256) void packw_kernel(
    const float* __restrict__ W, int N, uint32_t* __restrict__ out)
{
    const int n4 = blockIdx.x * 256 + threadIdx.x;
    const int k2 = blockIdx.y;
    const float4 e = *(const float4*)(W + (size_t)(2 * k2) * N + 4 * n4);
    const float4 o = *(const float4*)(W + (size_t)(2 * k2 + 1) * N + 4 * n4);
    uint4 r;
    r.x = pack_h2(e.x, o.x); r.y = pack_h2(e.y, o.y);
    r.z = pack_h2(e.z, o.z); r.w = pack_h2(e.w, o.w);
    *(uint4*)(out + (size_t)k2 * N + 4 * n4) = r;
}

// ---------------------------------------------------------------------------
// fp16 GEMM mainloop: CTA 128x128, 256 thr = 8 warps (2m x 4n), warp 64x32.
// 3-stage cp.async pipeline (wait_group 1), ldmatrix.x4 A fragments.
// As[m] pitch 36 words; Bs[k2] pitch 136 words.
// ---------------------------------------------------------------------------
#define AW 36
#define BW 136
#define STW (128 * AW + 32 * BW)          // words per stage = 8960
#define NST 3
#define GEMM_DYN (NST * STW * 4)          // 107520 bytes

__device__ __forceinline__ void gemm16_main(
    const uint32_t* __restrict__ Ag, const uint32_t* __restrict__ Wg,
    int ldw2, int m0, int ng, float acc[4][4][4])
{
    extern __shared__ __align__(16) uint32_t smw[];
    const uint32_t sbase = smem_u32(smw);

    const int t = threadIdx.x;
    const int lane = t & 31;
    const int warp = t >> 5;
    const int gid = lane >> 2, tg = lane & 3;
    const int wm = (warp & 1) * 64, wn = (warp >> 1) * 32;
    const int sr = t >> 3;
    const int si = (t & 7) * 4;

#pragma unroll
    for (int i = 0; i < 4; ++i)
#pragma unroll
        for (int j = 0; j < 4; ++j)
#pragma unroll
            for (int r = 0; r < 4; ++r) acc[i][j][r] = 0.0f;

    auto load_stage = [&](int kt, int st) {
        const uint32_t sa = sbase + (st * STW) * 4;
        const uint32_t sb = sa + (128 * AW) * 4;
#pragma unroll
        for (int rr = 0; rr < 4; ++rr)
            cpa16(sa + ((sr + rr * 32) * AW + si) * 4,
                  Ag + (size_t)(m0 + sr + rr * 32) * 512 + kt * 32 + si);
#pragma unroll
        for (int ii = 0; ii < 4; ++ii)
            cpa16(sb + (sr * BW + si + ii * 32) * 4,
                  Wg + (size_t)(kt * 32 + sr) * ldw2 + ng + si + ii * 32);
        asm volatile("cp.async.commit_group;" ::: "memory");
    };

    load_stage(0, 0);
    load_stage(1, 1);

    for (int kt = 0; kt < 16; ++kt) {
        const int cur = kt % NST;
        asm volatile("cp.async.wait_group 1;" ::: "memory");
        __syncthreads();
        if (kt + 2 < 16) load_stage(kt + 2, (kt + 2) % NST);

        const uint32_t sa = sbase + (cur * STW) * 4;
        const uint32_t* Bs = smw + cur * STW + 128 * AW;
        const uint32_t arow = (uint32_t)(lane & 15);
        const uint32_t ahalf = (uint32_t)(lane >> 4) * 4;

#pragma unroll
        for (int c = 0; c < 4; ++c) {
            uint32_t afr[4][4], bfr[4][2];
#pragma unroll
            for (int mf = 0; mf < 4; ++mf)
                ldmatrix_x4(afr[mf],
                    sa + ((wm + mf * 16 + arow) * AW + c * 8 + ahalf) * 4);
#pragma unroll
            for (int nf = 0; nf < 4; ++nf) {
                const int n = wn + nf * 8 + gid;
                bfr[nf][0] = Bs[(c * 8 + tg) * BW + n];
                bfr[nf][1] = Bs[(c * 8 + tg + 4) * BW + n];
            }
#pragma unroll
            for (int mf = 0; mf < 4; ++mf)
#pragma unroll
                for (int nf = 0; nf < 4; ++nf)
                    mma_f16(acc[mf][nf], afr[mf], bfr[nf]);
        }
    }
}

// qkv projection: grid (24, 64). Writes q/k/v as fp16 (q pre-scaled 0.125).
__global__ __launch_bounds__(256) void qkv_gemm_kernel(const float* __restrict__ bias)
{
    const int ng = blockIdx.x * 128;
    const int m0 = blockIdx.y * 128;
    const uint32_t* Ag = (ng < 1024) ? b_inq : b_inx;
    float acc[4][4][4];
    gemm16_main(Ag, b_w2, 3072, m0, ng, acc);

    const int t = threadIdx.x;
    const int lane = t & 31, warp = t >> 5;
    const int gid = lane >> 2, tg = lane & 3;
    const int wm = (warp & 1) * 64, wn = (warp >> 1) * 32;

    uint32_t* Og; int ccol; float scale;
    if (ng < 1024)       { Og = b_q; ccol = ng;        scale = 0.125f; }
    else if (ng < 2048)  { Og = b_k; ccol = ng - 1024; scale = 1.0f; }
    else                 { Og = b_v; ccol = ng - 2048; scale = 1.0f; }

#pragma unroll
    for (int nf = 0; nf < 4; ++nf) {
        const int cl = wn + nf * 8 + 2 * tg;
        const float b0 = bias[ng + cl], b1 = bias[ng + cl + 1];
#pragma unroll
        for (int mf = 0; mf < 4; ++mf) {
            const int row = m0 + wm + mf * 16 + gid;
            Og[(size_t)row * 512 + (ccol + cl) / 2] =
                pack_h2((acc[mf][nf][0] + b0) * scale,
                        (acc[mf][nf][1] + b1) * scale);
            Og[(size_t)(row + 8) * 512 + (ccol + cl) / 2] =
                pack_h2((acc[mf][nf][2] + b0) * scale,
                        (acc[mf][nf][3] + b1) * scale);
        }
    }
}

// output projection: grid (8, 64). Reads b_a (fp16), writes f32 out.
__global__ __launch_bounds__(256) void proj_gemm_kernel(
    const float* __restrict__ bias, float* __restrict__ out)
{
    const int ng = blockIdx.x * 128;
    const int m0 = blockIdx.y * 128;
    float acc[4][4][4];
    gemm16_main(b_a, b_p2, 1024, m0, ng, acc);

    const int t = threadIdx.x;
    const int lane = t & 31, warp = t >> 5;
    const int gid = lane >> 2, tg = lane & 3;
    const int wm = (warp & 1) * 64, wn = (warp >> 1) * 32;

#pragma unroll
    for (int nf = 0; nf < 4; ++nf) {
        const int cl = wn + nf * 8 + 2 * tg;
        const float b0 = bias[ng + cl], b1 = bias[ng + cl + 1];
#pragma unroll
        for (int mf = 0; mf < 4; ++mf) {
            const int row = m0 + wm + mf * 16 + gid;
            *(float2*)(out + (size_t)row * 1024 + ng + cl) =
                make_float2(acc[mf][nf][0] + b0, acc[mf][nf][1] + b1);
            *(float2*)(out + (size_t)(row + 8) * 1024 + ng + cl) =
                make_float2(acc[mf][nf][2] + b0, acc[mf][nf][3] + b1);
        }
    }
}

// ---------------------------------------------------------------------------
// fp16 flash attention, cp.async double-buffered K/V in NATURAL layout.
// Grid (8, 16, 8), 256 thr (8 warps x 16 q-rows).
// Qs[128][36], per stage: Ks[64][36], Vs[64][36] (words; rows = natural K/V).
// QK B-frags: direct words of K rows (conflict-free).
// PV B-frags: ldmatrix.x4.trans on V tiles (conflict-free at pitch 36).
// ---------------------------------------------------------------------------
#define QW   (128 * 36)
#define KVW  (64 * 36)
#define ATT_DYN ((QW + 4 * KVW) * 4)      // 55296 bytes

__global__ __launch_bounds__(256) void attn_kernel()
{
    extern __shared__ __align__(16) uint32_t sma[];
    const uint32_t sbase = smem_u32(sma);

    const int qb = blockIdx.x, h = blockIdx.y, b = blockIdx.z;
    const int t = threadIdx.x;
    const int warp = t >> 5, lane = t & 31;
    const int gid = lane >> 2, tg = lane & 3;
    const int r0 = warp * 16 + gid, r1 = r0 + 8;
    const size_t qrow0 = (size_t)(b * SEQ + qb * 128);
    const size_t kvbase = (size_t)(b * SEQ) * 512 + h * 32;

    // K/V stage loader: natural rows, 16B cp.async, 4 per thread
    auto load_kv = [&](int kb, int st) {
        const uint32_t kdst = sbase + (QW + st * 2 * KVW) * 4;
        const uint32_t vdst = kdst + KVW * 4;
#pragma unroll
        for (int i = 0; i < 2; ++i) {
            const int id = t + i * 256;           // 0..511
            const int row = id >> 3;
            const int cq = (id & 7) * 4;
            const size_t g = kvbase + (size_t)(kb * 64 + row) * 512 + cq;
            cpa16(kdst + (row * 36 + cq) * 4, b_k + g);
            cpa16(vdst + (row * 36 + cq) * 4, b_v + g);
        }
        asm volatile("cp.async.commit_group;" ::: "memory");
    };

    // prologue: stage Q (LDG->STS, one-time) + first K/V block
    load_kv(0, 0);
    {
        const int sr = t >> 3, si = (t & 7) * 4;
#pragma unroll
        for (int rr = 0; rr < 4; ++rr) {
            uint4 v = *(const uint4*)(b_q + (qrow0 + sr + rr * 32) * 512
                                      + h * 32 + si);
            *(uint4*)&sma[(sr + rr * 32) * 36 + si] = v;
        }
    }
    __syncthreads();

    uint32_t qf[4][4];
#pragma unroll
    for (int c = 0; c < 4; ++c) {
        qf[c][0] = sma[r0 * 36 + c * 8 + tg];
        qf[c][1] = sma[r1 * 36 + c * 8 + tg];
        qf[c][2] = sma[r0 * 36 + c * 8 + tg + 4];
        qf[c][3] = sma[r1 * 36 + c * 8 + tg + 4];
    }

    float m_i[2] = {-3.0e38f, -3.0e38f};
    float l_i[2] = {0.0f, 0.0f};
    float O[8][4];
#pragma unroll
    for (int nf = 0; nf < 8; ++nf)
#pragma unroll
        for (int r = 0; r < 4; ++r) O[nf][r] = 0.0f;

    const int nkb = 2 * qb + 2;

    for (int kb = 0; kb < nkb; ++kb) {
        const int st = kb & 1;
        asm volatile("cp.async.wait_group 0;" ::: "memory");
        __syncthreads();
        if (kb + 1 < nkb) load_kv(kb + 1, st ^ 1);

        const uint32_t* Ks = sma + QW + st * 2 * KVW;
        const uint32_t vbase = sbase + (QW + st * 2 * KVW + KVW) * 4;

        // S = Q K^T  (B-frags = natural K row words)
        float s[8][4];
#pragma unroll
        for (int nf = 0; nf < 8; ++nf)
#pragma unroll
            for (int r = 0; r < 4; ++r) s[nf][r] = 0.0f;
#pragma unroll
        for (int c = 0; c < 4; ++c)
#pragma unroll
            for (int nf = 0; nf < 8; ++nf) {
                uint32_t bb[2];
                const int key = nf * 8 + gid;
                bb[0] = Ks[key * 36 + c * 8 + tg];
                bb[1] = Ks[key * 36 + c * 8 + tg + 4];
                mma_f16(s[nf], qf[c], bb);
            }

        // causal mask (diagonal blocks only)
        if (kb >= 2 * qb) {
            const int grow0 = qb * 128 + r0;
            const int gcol0 = kb * 64 + 2 * tg;
#pragma unroll
            for (int nf = 0; nf < 8; ++nf) {
                int c = gcol0 + nf * 8;
                if (c     > grow0)     s[nf][0] = -10000.0f;
                if (c + 1 > grow0)     s[nf][1] = -10000.0f;
                if (c     > grow0 + 8) s[nf][2] = -10000.0f;
                if (c + 1 > grow0 + 8) s[nf][3] = -10000.0f;
            }
        }

        // online softmax
        float rm0 = s[0][0], rm1 = s[0][2];
#pragma unroll
        for (int nf = 0; nf < 8; ++nf) {
            rm0 = fmaxf(rm0, fmaxf(s[nf][0], s[nf][1]));
            rm1 = fmaxf(rm1, fmaxf(s[nf][2], s[nf][3]));
        }
        rm0 = fmaxf(rm0, __shfl_xor_sync(0xffffffffu, rm0, 1));
        rm0 = fmaxf(rm0, __shfl_xor_sync(0xffffffffu, rm0, 2));
        rm1 = fmaxf(rm1, __shfl_xor_sync(0xffffffffu, rm1, 1));
        rm1 = fmaxf(rm1, __shfl_xor_sync(0xffffffffu, rm1, 2));

        const float mn0 = fmaxf(m_i[0], rm0);
        const float mn1 = fmaxf(m_i[1], rm1);
        const float alpha0 = __expf(m_i[0] - mn0);
        const float alpha1 = __expf(m_i[1] - mn1);
        m_i[0] = mn0; m_i[1] = mn1;

        float ls0 = 0.0f, ls1 = 0.0f;
        uint32_t ph0[8], ph1[8];
#pragma unroll
        for (int nf = 0; nf < 8; ++nf) {
            float p0 = __expf(s[nf][0] - mn0);
            float p1 = __expf(s[nf][1] - mn0);
            float p2 = __expf(s[nf][2] - mn1);
            float p3 = __expf(s[nf][3] - mn1);
            ls0 += p0 + p1;
            ls1 += p2 + p3;
            ph0[nf] = pack_h2(p0, p1);
            ph1[nf] = pack_h2(p2, p3);
        }
        ls0 += __shfl_xor_sync(0xffffffffu, ls0, 1);
        ls0 += __shfl_xor_sync(0xffffffffu, ls0, 2);
        ls1 += __shfl_xor_sync(0xffffffffu, ls1, 1);
        ls1 += __shfl_xor_sync(0xffffffffu, ls1, 2);

        l_i[0] = l_i[0] * alpha0 + ls0;
        l_i[1] = l_i[1] * alpha1 + ls1;
#pragma unroll
        for (int nf = 0; nf < 8; ++nf) {
            O[nf][0] *= alpha0; O[nf][1] *= alpha0;
            O[nf][2] *= alpha1; O[nf][3] *= alpha1;
        }

        // O += P V : B-frags via ldmatrix.x4.trans on natural V tiles.
        // lane group g2 = lane>>3 selects tile: {nf even half-k lo, hi,
        // nf odd half-k lo, hi}; address row = V[c*16 + (g2&1)*8 + (lane&7)],
        // word offset = nf2*8 (+4 for odd nf).
#pragma unroll
        for (int c = 0; c < 4; ++c) {
            uint32_t af[4] = {ph0[2 * c], ph1[2 * c], ph0[2 * c + 1], ph1[2 * c + 1]};
#pragma unroll
            for (int nf2 = 0; nf2 < 4; ++nf2) {
                const int g2 = lane >> 3;
                const int vrow = c * 16 + ((g2 & 1) ? 8 : 0) + (lane & 7);
                const int vcol = nf2 * 8 + ((g2 >> 1) ? 4 : 0);
                uint32_t vb[4];
                ldmatrix_x4t(vb, vbase + (vrow * 36 + vcol) * 4);
                mma_f16(O[2 * nf2],     af, vb);       // vb[0],vb[1]
                mma_f16(O[2 * nf2 + 1], af, vb + 2);   // vb[2],vb[3]
            }
        }
    }

    // normalize, write fp16 merged-head output
    const float inv0 = 1.0f / l_i[0];
    const float inv1 = 1.0f / l_i[1];
#pragma unroll
    for (int nf = 0; nf < 8; ++nf) {
        b_a[(qrow0 + r0) * 512 + h * 32 + nf * 4 + tg] =
            pack_h2(O[nf][0] * inv0, O[nf][1] * inv0);
        b_a[(qrow0 + r1) * 512 + h * 32 + nf * 4 + tg] =
            pack_h2(O[nf][2] * inv1, O[nf][3] * inv1);
    }
}

// ---------------------------------------------------------------------------
// Launch
// ---------------------------------------------------------------------------
extern "C" void kernel_launch(void* const* d_in, const int* in_sizes, int n_in,
                              void* d_out, int out_size)
{
    const float* x     = (const float*)d_in[0];
    const float* query = (const float*)d_in[1];
    const float* attw  = (const float*)d_in[2];
    const float* attb  = (const float*)d_in[3];
    const float* projw = (const float*)d_in[4];
    const float* projb = (const float*)d_in[5];
    float* out = (float*)d_out;

    uint32_t *w2_, *p2_;
    cudaGetSymbolAddress((void**)&w2_, b_w2);
    cudaGetSymbolAddress((void**)&p2_, b_p2);

    cudaFuncSetAttribute(qkv_gemm_kernel,
                         cudaFuncAttributeMaxDynamicSharedMemorySize, GEMM_DYN);
    cudaFuncSetAttribute(proj_gemm_kernel,
                         cudaFuncAttributeMaxDynamicSharedMemorySize, GEMM_DYN);
    cudaFuncSetAttribute(attn_kernel,
                         cudaFuncAttributeMaxDynamicSharedMemorySize, ATT_DYN);

    // pre-passes: fp16 conversion + weight transpose-pack
    cvt_f16_kernel<<<dim3(8192, 2), 256>>>((const float4*)query, (const float4*)x);
    packw_kernel<<<dim3(3, 512), 256>>>(attw, 3 * NX, w2_);
    packw_kernel<<<dim3(1, 512), 256>>>(projw, NX, p2_);

    // q/k/v projections
    qkv_gemm_kernel<<<dim3(24, 64), 256, GEMM_DYN>>>(attb);

    // attention
    attn_kernel<<<dim3(8, NH, BSZ), 256, ATT_DYN>>>();

    // output projection
    proj_gemm_kernel<<<dim3(8, 64), 256, GEMM_DYN>>>(projb, out);
}